// round 6
// baseline (speedup 1.0000x reference)
#include <cuda_runtime.h>
#include <cstdint>

// x: [8192, 4096] fp32 row-major. loss = N*sum(x*x) - sum_d(colsum_d)^2
#define N_ROWS   8192
#define D_COLS   4096
#define ROW_F4   (D_COLS / 4)        // 1024 float4 per row

#define CBLK     2                   // column groups (2048 cols each)
#define RCHUNKS  256                 // row chunks
#define ROWS_PER_CHUNK (N_ROWS / RCHUNKS)   // 32
#define NBLOCKS  (CBLK * RCHUNKS)    // 512
#define NTHREADS 256

#define SUPER    16                  // chunks per super-group
#define NSUPER   (RCHUNKS / SUPER)   // 16

// Scratch (__device__ globals; no allocations allowed)
__device__ float4   g_part [RCHUNKS * ROW_F4];        // 4 MB level-1 colsum partials
__device__ float4   g_part2[CBLK * NSUPER * 512];     // 256 KB level-2
__device__ float    g_ss_part[NBLOCKS];               // 512 sumsq partials
__device__ float    g_colsq[CBLK];
__device__ unsigned g_cnt_super[CBLK * NSUPER];       // each resets itself
__device__ unsigned g_cnt_cg[CBLK];
__device__ unsigned g_cnt_final;

// block-reduce one float over 256 threads -> valid in thread 0
__device__ __forceinline__ float block_sum(float v, float* sh8, int t) {
    #pragma unroll
    for (int o = 16; o > 0; o >>= 1) v += __shfl_down_sync(0xffffffffu, v, o);
    if ((t & 31) == 0) sh8[t >> 5] = v;
    __syncthreads();
    float r = 0.f;
    if (t < 8) {
        r = sh8[t];
        #pragma unroll
        for (int o = 4; o > 0; o >>= 1) r += __shfl_down_sync(0xffu, r, o);
    }
    __syncthreads();
    return r;
}

__global__ __launch_bounds__(NTHREADS, 5)   // reg cap ~51 -> deep LDG batching
void stability_loss_kernel(const float* __restrict__ x, float* __restrict__ out)
{
    __shared__ float    sh_red[8];
    __shared__ unsigned sh_old;

    const int t     = threadIdx.x;
    const int b     = blockIdx.x;
    const int cg    = b & (CBLK - 1);     // 0..1
    const int chunk = b >> 1;             // 0..255
    const int sg    = chunk >> 4;         // super-group 0..15

    // ---------------- Phase 1: stream 2048 cols x 32 rows, 2 streams/thread --------
    {
        const float4* __restrict__ p0 = reinterpret_cast<const float4*>(x)
            + (size_t)chunk * ROWS_PER_CHUNK * ROW_F4 + cg * 512 + t;
        const float4* __restrict__ p1 = p0 + 256;

        float4 cs0 = make_float4(0.f, 0.f, 0.f, 0.f);
        float4 cs1 = make_float4(0.f, 0.f, 0.f, 0.f);
        float  ss  = 0.f;

        #pragma unroll 8
        for (int r = 0; r < ROWS_PER_CHUNK; ++r) {
            float4 a = p0[(size_t)r * ROW_F4];
            float4 c = p1[(size_t)r * ROW_F4];
            cs0.x += a.x; cs0.y += a.y; cs0.z += a.z; cs0.w += a.w;
            cs1.x += c.x; cs1.y += c.y; cs1.z += c.z; cs1.w += c.w;
            ss += a.x*a.x + a.y*a.y + a.z*a.z + a.w*a.w
                + c.x*c.x + c.y*c.y + c.z*c.z + c.w*c.w;
        }

        const size_t base = (size_t)chunk * ROW_F4 + cg * 512;
        g_part[base + t]       = cs0;
        g_part[base + 256 + t] = cs1;

        float tot = block_sum(ss, sh_red, t);
        if (t == 0) g_ss_part[b] = tot;
    }

    // ---------------- Level 1 -> 2: last arrival of 16 chunks reduces them ---------
    __threadfence();
    if (t == 0) sh_old = atomicAdd(&g_cnt_super[cg * NSUPER + sg], 1u);
    __syncthreads();
    if (sh_old != SUPER - 1) return;
    if (t == 0) g_cnt_super[cg * NSUPER + sg] = 0;   // reset for next graph replay

    {
        float4 s0 = make_float4(0.f, 0.f, 0.f, 0.f);
        float4 s1 = make_float4(0.f, 0.f, 0.f, 0.f);
        #pragma unroll 4
        for (int c = 0; c < SUPER; ++c) {
            const size_t base = (size_t)(sg * SUPER + c) * ROW_F4 + cg * 512;
            float4 v0 = __ldcg(&g_part[base + t]);
            float4 v1 = __ldcg(&g_part[base + 256 + t]);
            s0.x += v0.x; s0.y += v0.y; s0.z += v0.z; s0.w += v0.w;
            s1.x += v1.x; s1.y += v1.y; s1.z += v1.z; s1.w += v1.w;
        }
        const size_t o2 = (size_t)(cg * NSUPER + sg) * 512;
        g_part2[o2 + t]       = s0;
        g_part2[o2 + 256 + t] = s1;
    }

    // ---------------- Level 2 -> colsq: last super-deputy of this cg ---------------
    __threadfence();
    __syncthreads();
    if (t == 0) sh_old = atomicAdd(&g_cnt_cg[cg], 1u);
    __syncthreads();
    if (sh_old != NSUPER - 1) return;
    if (t == 0) g_cnt_cg[cg] = 0;

    {
        float4 s0 = make_float4(0.f, 0.f, 0.f, 0.f);
        float4 s1 = make_float4(0.f, 0.f, 0.f, 0.f);
        #pragma unroll 4
        for (int s = 0; s < NSUPER; ++s) {
            const size_t o2 = (size_t)(cg * NSUPER + s) * 512;
            float4 v0 = __ldcg(&g_part2[o2 + t]);
            float4 v1 = __ldcg(&g_part2[o2 + 256 + t]);
            s0.x += v0.x; s0.y += v0.y; s0.z += v0.z; s0.w += v0.w;
            s1.x += v1.x; s1.y += v1.y; s1.z += v1.z; s1.w += v1.w;
        }
        float sq = s0.x*s0.x + s0.y*s0.y + s0.z*s0.z + s0.w*s0.w
                 + s1.x*s1.x + s1.y*s1.y + s1.z*s1.z + s1.w*s1.w;
        float csq = block_sum(sq, sh_red, t);
        if (t == 0) g_colsq[cg] = csq;
    }

    // ---------------- Final: last cg-deputy folds everything -----------------------
    __threadfence();
    __syncthreads();
    if (t == 0) sh_old = atomicAdd(&g_cnt_final, 1u);
    __syncthreads();
    if (sh_old != CBLK - 1) return;
    if (t == 0) g_cnt_final = 0;

    {
        float ss = __ldcg(&g_ss_part[t]) + __ldcg(&g_ss_part[t + 256]);
        float cq = (t < CBLK) ? __ldcg(&g_colsq[t]) : 0.f;

        #pragma unroll
        for (int o = 16; o > 0; o >>= 1) {
            ss += __shfl_down_sync(0xffffffffu, ss, o);
            cq += __shfl_down_sync(0xffffffffu, cq, o);
        }
        __shared__ float sh_a[8], sh_b[8];
        if ((t & 31) == 0) { sh_a[t >> 5] = ss; sh_b[t >> 5] = cq; }
        __syncthreads();
        if (t < 8) {
            float a = sh_a[t], c2 = sh_b[t];
            #pragma unroll
            for (int o = 4; o > 0; o >>= 1) {
                a  += __shfl_down_sync(0xffu, a,  o);
                c2 += __shfl_down_sync(0xffu, c2, o);
            }
            if (t == 0)
                out[0] = (float)N_ROWS * a - c2;
        }
    }
}

extern "C" void kernel_launch(void* const* d_in, const int* in_sizes, int n_in,
                              void* d_out, int out_size)
{
    const float* x = (const float*)d_in[0];
    float* out = (float*)d_out;
    (void)in_sizes; (void)n_in; (void)out_size;

    stability_loss_kernel<<<NBLOCKS, NTHREADS>>>(x, out);
}

// round 7
// speedup vs baseline: 1.1723x; 1.1723x over previous
#include <cuda_runtime.h>
#include <cstdint>

// x: [8192, 4096] fp32 row-major. loss = N*sum(x*x) - sum_d(colsum_d)^2
#define N_ROWS   8192
#define D_COLS   4096
#define ROW_F4   (D_COLS / 4)               // 1024 float4 per row

#define CBLK     4                          // column groups (1024 cols each)
#define RCHUNKS  256                        // row chunks
#define ROWS_PER_CHUNK (N_ROWS / RCHUNKS)   // 32
#define NBLOCKS  (CBLK * RCHUNKS)           // 1024
#define NTHREADS 256

#define SUPER    16                         // chunks per super-group
#define NSUPER   (RCHUNKS / SUPER)          // 16

// Scratch (__device__ globals; no allocations allowed)
__device__ float4   g_part [RCHUNKS * ROW_F4];        // 4 MB level-1 colsum partials
__device__ float4   g_part2[CBLK * NSUPER * 256];     // 256 KB level-2
__device__ float    g_ss_part[NBLOCKS];               // 1024 sumsq partials
__device__ float    g_colsq[CBLK];
__device__ unsigned g_cnt_super[CBLK * NSUPER];       // each resets itself
__device__ unsigned g_cnt_cg[CBLK];
__device__ unsigned g_cnt_final;

// block-reduce one float over 256 threads -> valid in thread 0
__device__ __forceinline__ float block_sum(float v, float* sh8, int t) {
    #pragma unroll
    for (int o = 16; o > 0; o >>= 1) v += __shfl_down_sync(0xffffffffu, v, o);
    if ((t & 31) == 0) sh8[t >> 5] = v;
    __syncthreads();
    float r = 0.f;
    if (t < 8) {
        r = sh8[t];
        #pragma unroll
        for (int o = 4; o > 0; o >>= 1) r += __shfl_down_sync(0xffu, r, o);
    }
    __syncthreads();
    return r;
}

__global__ __launch_bounds__(NTHREADS, 8)   // force <=32 regs -> 8 CTAs/SM capacity
void stability_loss_kernel(const float* __restrict__ x, float* __restrict__ out)
{
    __shared__ float    sh_red[8];
    __shared__ unsigned sh_old;

    const int t     = threadIdx.x;
    const int b     = blockIdx.x;
    const int cg    = b & (CBLK - 1);       // 0..3
    const int chunk = b >> 2;               // 0..255
    const int sg    = chunk >> 4;           // super-group 0..15

    // ------------- Phase 1: stream 1024 cols x 32 rows, 1 float4/thread -------------
    {
        const float4* __restrict__ p = reinterpret_cast<const float4*>(x)
            + (size_t)chunk * ROWS_PER_CHUNK * ROW_F4 + cg * 256 + t;

        float4 cs = make_float4(0.f, 0.f, 0.f, 0.f);
        float  ss = 0.f;

        #pragma unroll 8
        for (int r = 0; r < ROWS_PER_CHUNK; ++r) {
            float4 v = p[(size_t)r * ROW_F4];
            cs.x += v.x; cs.y += v.y; cs.z += v.z; cs.w += v.w;
            ss   += v.x*v.x + v.y*v.y + v.z*v.z + v.w*v.w;
        }

        g_part[(size_t)chunk * ROW_F4 + cg * 256 + t] = cs;

        float tot = block_sum(ss, sh_red, t);
        if (t == 0) g_ss_part[b] = tot;
    }

    // ------------- Level 1 -> 2: last arrival of 16 chunks reduces them -------------
    __threadfence();
    if (t == 0) sh_old = atomicAdd(&g_cnt_super[cg * NSUPER + sg], 1u);
    __syncthreads();
    if (sh_old != SUPER - 1) return;
    if (t == 0) g_cnt_super[cg * NSUPER + sg] = 0;   // reset for next graph replay

    {
        float4 s = make_float4(0.f, 0.f, 0.f, 0.f);
        #pragma unroll 4
        for (int c = 0; c < SUPER; ++c) {
            float4 v = __ldcg(&g_part[(size_t)(sg * SUPER + c) * ROW_F4 + cg * 256 + t]);
            s.x += v.x; s.y += v.y; s.z += v.z; s.w += v.w;
        }
        g_part2[(size_t)(cg * NSUPER + sg) * 256 + t] = s;
    }

    // ------------- Level 2 -> colsq: last super-deputy of this cg --------------------
    __threadfence();
    __syncthreads();
    if (t == 0) sh_old = atomicAdd(&g_cnt_cg[cg], 1u);
    __syncthreads();
    if (sh_old != NSUPER - 1) return;
    if (t == 0) g_cnt_cg[cg] = 0;

    {
        float4 s = make_float4(0.f, 0.f, 0.f, 0.f);
        #pragma unroll 4
        for (int sgi = 0; sgi < NSUPER; ++sgi) {
            float4 v = __ldcg(&g_part2[(size_t)(cg * NSUPER + sgi) * 256 + t]);
            s.x += v.x; s.y += v.y; s.z += v.z; s.w += v.w;
        }
        float sq = s.x*s.x + s.y*s.y + s.z*s.z + s.w*s.w;
        float csq = block_sum(sq, sh_red, t);
        if (t == 0) g_colsq[cg] = csq;
    }

    // ------------- Final: last cg-deputy folds everything ----------------------------
    __threadfence();
    __syncthreads();
    if (t == 0) sh_old = atomicAdd(&g_cnt_final, 1u);
    __syncthreads();
    if (sh_old != CBLK - 1) return;
    if (t == 0) g_cnt_final = 0;

    {
        float ss = 0.f;
        #pragma unroll
        for (int i = 0; i < NBLOCKS / NTHREADS; ++i)      // 4 each
            ss += __ldcg(&g_ss_part[t + i * NTHREADS]);
        float cq = (t < CBLK) ? __ldcg(&g_colsq[t]) : 0.f;

        #pragma unroll
        for (int o = 16; o > 0; o >>= 1) {
            ss += __shfl_down_sync(0xffffffffu, ss, o);
            cq += __shfl_down_sync(0xffffffffu, cq, o);
        }
        __shared__ float sh_a[8], sh_b[8];
        if ((t & 31) == 0) { sh_a[t >> 5] = ss; sh_b[t >> 5] = cq; }
        __syncthreads();
        if (t < 8) {
            float a = sh_a[t], c2 = sh_b[t];
            #pragma unroll
            for (int o = 4; o > 0; o >>= 1) {
                a  += __shfl_down_sync(0xffu, a,  o);
                c2 += __shfl_down_sync(0xffu, c2, o);
            }
            if (t == 0)
                out[0] = (float)N_ROWS * a - c2;
        }
    }
}

extern "C" void kernel_launch(void* const* d_in, const int* in_sizes, int n_in,
                              void* d_out, int out_size)
{
    const float* x = (const float*)d_in[0];
    float* out = (float*)d_out;
    (void)in_sizes; (void)n_in; (void)out_size;

    stability_loss_kernel<<<NBLOCKS, NTHREADS>>>(x, out);
}